// round 14
// baseline (speedup 1.0000x reference)
#include <cuda_runtime.h>
#include <math.h>

#define BB 128
#define NN 64
#define DD 64
#define ROWS (BB*NN)      // 8192 (b,n) rows
#define BNN  (BB*NN*NN)   // 524288 output rows

// ---------------- scratch (device globals: no allocations allowed) ----------
__device__ float K_  [ROWS*DD];
__device__ float Q_  [ROWS*DD];
__device__ float CAE_[ROWS*DD];
__device__ float EA_ [ROWS*DD];
__device__ float EP_ [ROWS*DD];
__device__ float AVA_[ROWS*DD];
__device__ float DV_ [ROWS*DD];
__device__ float AB_ [ROWS*DD];
__device__ float AP_ [ROWS*DD];
__device__ float DB_ [ROWS*DD];
__device__ float S_  [ROWS*DD];
__device__ float WT_ [ROWS*NN];
__device__ float PC_ [ROWS*DD];
__device__ float SX_ [ROWS*DD];
__device__ float SCOL_[DD];
// LN moment machinery
__device__ float SA_  [ROWS];
__device__ float SA2_ [ROWS];
__device__ float SP_  [ROWS];
__device__ float SP2_ [ROWS];
__device__ float SDV_ [ROWS];
__device__ float SDV2_[ROWS];
__device__ float SADV_[ROWS];
__device__ float SPDV_[ROWS];
__device__ float SS_  [ROWS];
__device__ float SS2_ [ROWS];
__device__ float M1P_ [ROWS];
__device__ float M1_  [ROWS*NN];
__device__ float M2_  [ROWS*NN];

// Precise gelu (erff) — used only to build the LUT (kernelA).
__device__ __forceinline__ float gelu_exact(float x){
    return 0.5f*x*(1.0f + erff(x*0.70710678118654752f));
}

// MUFU-based gelu (A&S 7.1.26, |err|<=1.5e-7 abs) — no shared memory.
__device__ __forceinline__ float gelu_as(float x){
    float z = fabsf(x) * 0.70710678118654752f;
    float t = __fdividef(1.0f, fmaf(0.3275911f, z, 1.0f));
    float p = fmaf(t, 1.061405429f, -1.453152027f);
    p = fmaf(t, p, 1.421413741f);
    p = fmaf(t, p, -0.284496736f);
    p = fmaf(t, p, 0.254829592f);
    p = p * t;
    float e = __expf(-z*z);
    float erfz = fmaf(-p, e, 1.0f);
    float cdf  = fmaf(copysignf(erfz, x), 0.5f, 0.5f);
    return x * cdf;
}

// 768-segment piecewise-linear gelu LUT over [-6,6] (kernelA only).
#define LUTN 768
__device__ __forceinline__ void build_gelu_lut(float2* lut, int t, int nthreads){
    for (int i = t; i < LUTN; i += nthreads){
        float x0 = (i - 384) * 0.015625f;
        float x1 = x0 + 0.015625f;
        float y0 = gelu_exact(x0);
        float y1 = gelu_exact(x1);
        float k = y1 - y0;
        lut[i] = make_float2(k, fmaf(-(float)i, k, y0));
    }
}
__device__ __forceinline__ float gelu_lut(float x, const float2* lut){
    float u = fmaf(x, 64.0f, 384.0f);
    int i = (int)u;
    i = max(0, min(i, LUTN - 1));
    float2 e = lut[i];
    return fmaf(u, e.x, e.y);
}

__device__ __forceinline__ unsigned tf32_rne(float x){
    unsigned u;
    asm("cvt.rna.tf32.f32 %0, %1;" : "=r"(u) : "f"(x));
    return u;
}

__device__ __forceinline__ void mma_tf32(float& c0, float& c1, float& c2, float& c3,
                                         unsigned a0, unsigned a1, unsigned a2, unsigned a3,
                                         unsigned b0, unsigned b1){
    asm volatile("mma.sync.aligned.m16n8k8.row.col.f32.tf32.tf32.f32 "
                 "{%0,%1,%2,%3}, {%4,%5,%6,%7}, {%8,%9}, {%0,%1,%2,%3};"
                 : "+f"(c0), "+f"(c1), "+f"(c2), "+f"(c3)
                 : "r"(a0), "r"(a1), "r"(a2), "r"(a3), "r"(b0), "r"(b1));
}

// ================= Kernel A: per-(b,n) fused encoder =========================
__global__ void __launch_bounds__(256)
kernelA(const float* __restrict__ states, const float* __restrict__ policies,
        const float* __restrict__ actions,
        const float* __restrict__ W_se, const float* __restrict__ b_se,
        const float* __restrict__ W_k,  const float* __restrict__ b_k,
        const float* __restrict__ W_q,  const float* __restrict__ b_q,
        const float* __restrict__ W_sap,const float* __restrict__ b_sap,
        const float* __restrict__ W_av, const float* __restrict__ b_av,
        const float* __restrict__ g1v,  const float* __restrict__ beta1,
        const float* __restrict__ W_ca, const float* __restrict__ b_ca,
        const float* __restrict__ g2,   const float* __restrict__ beta2,
        const float* __restrict__ W_f1, const float* __restrict__ b_f1)
{
    __shared__ float st[16][128];
    __shared__ float ac[16][32], po[16][32];
    __shared__ float sse[16][64], sea[16][64], sep[16][64], sdv[16][64];
    __shared__ float scae[16][64];
    __shared__ float sg1[64], sb1[64];
    __shared__ float red[16][2];
    __shared__ float2 sLut[LUTN];

    int t = threadIdx.x, d = t & 63, g = t >> 6;
    int lane = t & 31, wig = (t >> 5) & 1;
    int row0 = blockIdx.x*16;
    int r0 = g*4;

    build_gelu_lut(sLut, t, 256);
    #pragma unroll
    for (int j = 0; j < 8; j++){
        int idx = t + j*256;
        st[idx >> 7][idx & 127] = states[row0*128 + idx];
    }
    #pragma unroll
    for (int j = 0; j < 2; j++){
        int idx = t + j*256;
        ac[idx >> 5][idx & 31] = actions[row0*32 + idx];
        po[idx >> 5][idx & 31] = policies[row0*32 + idx];
    }
    if (t < 64) sg1[t] = g1v[t];
    else if (t < 128) sb1[t-64] = beta1[t-64];
    __syncthreads();

    float a0 = b_se[d], a1 = a0, a2 = a0, a3 = a0;
    #pragma unroll 8
    for (int k = 0; k < 128; k++){
        float w = W_se[k*64 + d];
        a0 = fmaf(st[r0  ][k], w, a0);
        a1 = fmaf(st[r0+1][k], w, a1);
        a2 = fmaf(st[r0+2][k], w, a2);
        a3 = fmaf(st[r0+3][k], w, a3);
    }
    float se0 = gelu_lut(a0, sLut), se1 = gelu_lut(a1, sLut);
    float se2 = gelu_lut(a2, sLut), se3 = gelu_lut(a3, sLut);
    sse[r0][d] = se0; sse[r0+1][d] = se1; sse[r0+2][d] = se2; sse[r0+3][d] = se3;
    __syncthreads();

    float k0 = b_k[d], k1 = k0, k2 = k0, k3 = k0;
    float q0 = b_q[d], q1 = q0, q2 = q0, q3 = q0;
    #pragma unroll 8
    for (int k = 0; k < 64; k++){
        float wk = W_k[k*64 + d];
        float wq = W_q[k*64 + d];
        float s0 = sse[r0][k], s1 = sse[r0+1][k], s2 = sse[r0+2][k], s3 = sse[r0+3][k];
        k0 = fmaf(s0, wk, k0); k1 = fmaf(s1, wk, k1); k2 = fmaf(s2, wk, k2); k3 = fmaf(s3, wk, k3);
        q0 = fmaf(s0, wq, q0); q1 = fmaf(s1, wq, q1); q2 = fmaf(s2, wq, q2); q3 = fmaf(s3, wq, q3);
    }
    K_[(row0+r0  )*64 + d] = gelu_lut(k0, sLut);
    K_[(row0+r0+1)*64 + d] = gelu_lut(k1, sLut);
    K_[(row0+r0+2)*64 + d] = gelu_lut(k2, sLut);
    K_[(row0+r0+3)*64 + d] = gelu_lut(k3, sLut);
    Q_[(row0+r0  )*64 + d] = gelu_lut(q0, sLut);
    Q_[(row0+r0+1)*64 + d] = gelu_lut(q1, sLut);
    Q_[(row0+r0+2)*64 + d] = gelu_lut(q2, sLut);
    Q_[(row0+r0+3)*64 + d] = gelu_lut(q3, sLut);

    float c0 = b_ca[d], c1 = c0, c2 = c0, c3 = c0;
    #pragma unroll 8
    for (int k = 0; k < 128; k++){
        float w = W_ca[k*64 + d];
        c0 = fmaf(st[r0  ][k], w, c0);
        c1 = fmaf(st[r0+1][k], w, c1);
        c2 = fmaf(st[r0+2][k], w, c2);
        c3 = fmaf(st[r0+3][k], w, c3);
    }
    float v0 = gelu_lut(c0, sLut) + se0, v1 = gelu_lut(c1, sLut) + se1;
    float v2 = gelu_lut(c2, sLut) + se2, v3 = gelu_lut(c3, sLut) + se3;
    {
        float s0 = v0, s1 = v1, s2 = v2, s3 = v3;
        #pragma unroll
        for (int o = 16; o > 0; o >>= 1){
            s0 += __shfl_xor_sync(0xffffffffu, s0, o);
            s1 += __shfl_xor_sync(0xffffffffu, s1, o);
            s2 += __shfl_xor_sync(0xffffffffu, s2, o);
            s3 += __shfl_xor_sync(0xffffffffu, s3, o);
        }
        if (lane == 0){ red[r0][wig]=s0; red[r0+1][wig]=s1; red[r0+2][wig]=s2; red[r0+3][wig]=s3; }
    }
    __syncthreads();
    float m0 = (red[r0][0]+red[r0][1])*(1.0f/64.0f);
    float m1v= (red[r0+1][0]+red[r0+1][1])*(1.0f/64.0f);
    float m2v= (red[r0+2][0]+red[r0+2][1])*(1.0f/64.0f);
    float m3v= (red[r0+3][0]+red[r0+3][1])*(1.0f/64.0f);
    __syncthreads();
    float e0 = v0-m0, e1 = v1-m1v, e2 = v2-m2v, e3 = v3-m3v;
    {
        float s0=e0*e0, s1=e1*e1, s2=e2*e2, s3=e3*e3;
        #pragma unroll
        for (int o = 16; o > 0; o >>= 1){
            s0 += __shfl_xor_sync(0xffffffffu, s0, o);
            s1 += __shfl_xor_sync(0xffffffffu, s1, o);
            s2 += __shfl_xor_sync(0xffffffffu, s2, o);
            s3 += __shfl_xor_sync(0xffffffffu, s3, o);
        }
        if (lane == 0){ red[r0][wig]=s0; red[r0+1][wig]=s1; red[r0+2][wig]=s2; red[r0+3][wig]=s3; }
    }
    __syncthreads();
    {
        float gd = g2[d], bd = beta2[d];
        float var0 = (red[r0][0]+red[r0][1])*(1.0f/64.0f);
        float var1 = (red[r0+1][0]+red[r0+1][1])*(1.0f/64.0f);
        float var2 = (red[r0+2][0]+red[r0+2][1])*(1.0f/64.0f);
        float var3 = (red[r0+3][0]+red[r0+3][1])*(1.0f/64.0f);
        float ca0 = e0*rsqrtf(var0+1e-5f)*gd + bd;
        float ca1 = e1*rsqrtf(var1+1e-5f)*gd + bd;
        float ca2 = e2*rsqrtf(var2+1e-5f)*gd + bd;
        float ca3 = e3*rsqrtf(var3+1e-5f)*gd + bd;
        CAE_[(row0+r0  )*64+d] = ca0;  scae[r0  ][d] = ca0;
        CAE_[(row0+r0+1)*64+d] = ca1;  scae[r0+1][d] = ca1;
        CAE_[(row0+r0+2)*64+d] = ca2;  scae[r0+2][d] = ca2;
        CAE_[(row0+r0+3)*64+d] = ca3;  scae[r0+3][d] = ca3;
    }
    __syncthreads();

    float b0 = b_sap[d], b1 = b0, b2 = b0, b3 = b0;
    #pragma unroll 8
    for (int k = 0; k < 128; k++){
        float w = W_sap[k*64 + d];
        b0 = fmaf(st[r0  ][k], w, b0);
        b1 = fmaf(st[r0+1][k], w, b1);
        b2 = fmaf(st[r0+2][k], w, b2);
        b3 = fmaf(st[r0+3][k], w, b3);
    }
    float aA0=b0,aA1=b1,aA2=b2,aA3=b3, aP0=b0,aP1=b1,aP2=b2,aP3=b3;
    #pragma unroll 8
    for (int k = 0; k < 32; k++){
        float w = W_sap[(128 + k)*64 + d];
        aA0 = fmaf(ac[r0  ][k], w, aA0); aP0 = fmaf(po[r0  ][k], w, aP0);
        aA1 = fmaf(ac[r0+1][k], w, aA1); aP1 = fmaf(po[r0+1][k], w, aP1);
        aA2 = fmaf(ac[r0+2][k], w, aA2); aP2 = fmaf(po[r0+2][k], w, aP2);
        aA3 = fmaf(ac[r0+3][k], w, aA3); aP3 = fmaf(po[r0+3][k], w, aP3);
    }
    float ea0=gelu_lut(aA0,sLut), ea1=gelu_lut(aA1,sLut), ea2=gelu_lut(aA2,sLut), ea3=gelu_lut(aA3,sLut);
    float ep0=gelu_lut(aP0,sLut), ep1=gelu_lut(aP1,sLut), ep2=gelu_lut(aP2,sLut), ep3=gelu_lut(aP3,sLut);
    sea[r0][d]=ea0; sea[r0+1][d]=ea1; sea[r0+2][d]=ea2; sea[r0+3][d]=ea3;
    sep[r0][d]=ep0; sep[r0+1][d]=ep1; sep[r0+2][d]=ep2; sep[r0+3][d]=ep3;
    EA_[(row0+r0  )*64+d]=ea0; EA_[(row0+r0+1)*64+d]=ea1; EA_[(row0+r0+2)*64+d]=ea2; EA_[(row0+r0+3)*64+d]=ea3;
    EP_[(row0+r0  )*64+d]=ep0; EP_[(row0+r0+1)*64+d]=ep1; EP_[(row0+r0+2)*64+d]=ep2; EP_[(row0+r0+3)*64+d]=ep3;
    __syncthreads();

    float vA0=b_av[d],vA1=vA0,vA2=vA0,vA3=vA0, vP0=vA0,vP1=vA0,vP2=vA0,vP3=vA0;
    #pragma unroll 8
    for (int k = 0; k < 64; k++){
        float w = W_av[k*64 + d];
        vA0 = fmaf(sea[r0  ][k], w, vA0); vP0 = fmaf(sep[r0  ][k], w, vP0);
        vA1 = fmaf(sea[r0+1][k], w, vA1); vP1 = fmaf(sep[r0+1][k], w, vP1);
        vA2 = fmaf(sea[r0+2][k], w, vA2); vP2 = fmaf(sep[r0+2][k], w, vP2);
        vA3 = fmaf(sea[r0+3][k], w, vA3); vP3 = fmaf(sep[r0+3][k], w, vP3);
    }
    float av0=gelu_lut(vA0,sLut), av1=gelu_lut(vA1,sLut), av2=gelu_lut(vA2,sLut), av3=gelu_lut(vA3,sLut);
    float dv0=gelu_lut(vP0,sLut)-av0, dv1=gelu_lut(vP1,sLut)-av1;
    float dv2=gelu_lut(vP2,sLut)-av2, dv3=gelu_lut(vP3,sLut)-av3;
    AVA_[(row0+r0  )*64+d]=av0; AVA_[(row0+r0+1)*64+d]=av1; AVA_[(row0+r0+2)*64+d]=av2; AVA_[(row0+r0+3)*64+d]=av3;
    DV_ [(row0+r0  )*64+d]=dv0; DV_ [(row0+r0+1)*64+d]=dv1; DV_ [(row0+r0+2)*64+d]=dv2; DV_ [(row0+r0+3)*64+d]=dv3;
    sdv[r0][d]=dv0; sdv[r0+1][d]=dv1; sdv[r0+2][d]=dv2; sdv[r0+3][d]=dv3;
    __syncthreads();

    float fa0=0,fa1=0,fa2=0,fa3=0, fp0=0,fp1=0,fp2=0,fp3=0, fd0=0,fd1=0,fd2=0,fd3=0;
    #pragma unroll 8
    for (int k = 0; k < 64; k++){
        float wb = W_f1[(64 + k)*64 + d] * sg1[k];
        fa0 = fmaf(sea[r0  ][k], wb, fa0); fp0 = fmaf(sep[r0  ][k], wb, fp0); fd0 = fmaf(sdv[r0  ][k], wb, fd0);
        fa1 = fmaf(sea[r0+1][k], wb, fa1); fp1 = fmaf(sep[r0+1][k], wb, fp1); fd1 = fmaf(sdv[r0+1][k], wb, fd1);
        fa2 = fmaf(sea[r0+2][k], wb, fa2); fp2 = fmaf(sep[r0+2][k], wb, fp2); fd2 = fmaf(sdv[r0+2][k], wb, fd2);
        fa3 = fmaf(sea[r0+3][k], wb, fa3); fp3 = fmaf(sep[r0+3][k], wb, fp3); fd3 = fmaf(sdv[r0+3][k], wb, fd3);
    }
    AB_[(row0+r0  )*64+d]=fa0; AB_[(row0+r0+1)*64+d]=fa1; AB_[(row0+r0+2)*64+d]=fa2; AB_[(row0+r0+3)*64+d]=fa3;
    AP_[(row0+r0  )*64+d]=fp0; AP_[(row0+r0+1)*64+d]=fp1; AP_[(row0+r0+2)*64+d]=fp2; AP_[(row0+r0+3)*64+d]=fp3;
    DB_[(row0+r0  )*64+d]=fd0; DB_[(row0+r0+1)*64+d]=fd1; DB_[(row0+r0+2)*64+d]=fd2; DB_[(row0+r0+3)*64+d]=fd3;

    float pc0 = b_f1[d], pc1 = pc0, pc2 = pc0, pc3 = pc0, pcc = 0.f;
    #pragma unroll 8
    for (int k = 0; k < 64; k++){
        float wt = W_f1[k*64 + d];
        float wb = W_f1[(64 + k)*64 + d];
        pcc = fmaf(sb1[k], wb, pcc);
        pc0 = fmaf(scae[r0  ][k], wt, pc0);
        pc1 = fmaf(scae[r0+1][k], wt, pc1);
        pc2 = fmaf(scae[r0+2][k], wt, pc2);
        pc3 = fmaf(scae[r0+3][k], wt, pc3);
    }
    PC_[(row0+r0  )*64+d] = pc0 + pcc;
    PC_[(row0+r0+1)*64+d] = pc1 + pcc;
    PC_[(row0+r0+2)*64+d] = pc2 + pcc;
    PC_[(row0+r0+3)*64+d] = pc3 + pcc;
}

// ================= Kernel B: per-b softmax + S + per-x stats ================
__global__ void __launch_bounds__(256)
kernelB(float* __restrict__ outW)
{
    __shared__ float sK[64*65];
    __shared__ float sA[64*65];
    __shared__ float sq[4][64];
    __shared__ float sw[4][64];
    __shared__ float red[4][2];
    __shared__ float red3[4][2][3];

    int t = threadIdx.x, d = t & 63, g = t >> 6;
    int lane = t & 31, wig = (t >> 5) & 1;
    int b = blockIdx.x >> 1, half = blockIdx.x & 1;
    const int base = b*NN*DD;

    for (int jj = 0; jj < 16; jj++){
        int j = jj*4 + g;
        sK[j*65 + d] = K_  [base + j*64 + d];
        sA[j*65 + d] = AVA_[base + j*64 + d];
    }
    __syncthreads();

    for (int xi = 0; xi < 8; xi++){
        int x = half*32 + xi*4 + g;
        int rowx = b*64 + x;
        sq[g][d] = Q_[rowx*64 + d];
        __syncthreads();

        float s0 = 0.f, s1 = 0.f;
        #pragma unroll 8
        for (int k = 0; k < 64; k += 2){
            s0 = fmaf(sq[g][k],   sK[d*65 + k],   s0);
            s1 = fmaf(sq[g][k+1], sK[d*65 + k+1], s1);
        }
        float s = (s0 + s1) * 0.125f;

        float mx = s;
        #pragma unroll
        for (int o = 16; o > 0; o >>= 1) mx = fmaxf(mx, __shfl_xor_sync(0xffffffffu, mx, o));
        if (lane == 0) red[g][wig] = mx;
        __syncthreads();
        mx = fmaxf(red[g][0], red[g][1]);
        float e  = expf(s - mx);
        float ss = e;
        #pragma unroll
        for (int o = 16; o > 0; o >>= 1) ss += __shfl_xor_sync(0xffffffffu, ss, o);
        __syncthreads();
        if (lane == 0) red[g][wig] = ss;
        __syncthreads();
        float w = e / (red[g][0] + red[g][1]);

        sw[g][d] = w;
        WT_[rowx*64 + d] = w;
        if (outW) outW[rowx*64 + d] = w;
        __syncthreads();

        float S0 = 0.f, S1 = 0.f;
        #pragma unroll 8
        for (int i = 0; i < 64; i += 2){
            S0 = fmaf(sw[g][i],   sA[(i  )*65 + d], S0);
            S1 = fmaf(sw[g][i+1], sA[(i+1)*65 + d], S1);
        }
        float Sd = S0 + S1;
        S_[rowx*64 + d] = Sd;

        float ep = EP_[rowx*64 + d];
        float t1 = Sd, t2 = Sd*Sd, t3 = ep*Sd;
        #pragma unroll
        for (int o = 16; o > 0; o >>= 1){
            t1 += __shfl_xor_sync(0xffffffffu, t1, o);
            t2 += __shfl_xor_sync(0xffffffffu, t2, o);
            t3 += __shfl_xor_sync(0xffffffffu, t3, o);
        }
        if (lane == 0){ red3[g][wig][0]=t1; red3[g][wig][1]=t2; red3[g][wig][2]=t3; }
        __syncthreads();
        if (d == 0){
            SS_ [rowx] = red3[g][0][0] + red3[g][1][0];
            SS2_[rowx] = red3[g][0][1] + red3[g][1][1];
            M1P_[rowx] = red3[g][0][2] + red3[g][1][2];
        }
        __syncthreads();
    }
}

// ================= Kernel B23: fused B2 (cross-dots/moments) + B3 (SX) ======
__global__ void __launch_bounds__(256)
kernelB23(const float* __restrict__ g1v, const float* __restrict__ W_f1)
{
    __shared__ __align__(16) float uSm[9344];   // 37376 bytes

    int t = threadIdx.x;

    if (blockIdx.x < 512){
        float* sEA = uSm;             // 64*65
        float* sDV = uSm + 4160;      // 64*65
        float* sS  = uSm + 8320;      // 16*64

        int xi = t >> 6, y = t & 63;
        int b = blockIdx.x >> 2, q = blockIdx.x & 3;
        const int base = b*4096;

        for (int jj = 0; jj < 16; jj++){
            int j = jj*4 + xi;
            sEA[j*65 + y] = EA_[base + j*64 + y];
            sDV[j*65 + y] = DV_[base + j*64 + y];
        }
        for (int s4 = 0; s4 < 4; s4++){
            int xl = s4*4 + xi;
            sS[xl*64 + y] = S_[(b*64 + q*16 + xl)*64 + y];
        }
        __syncthreads();

        #pragma unroll
        for (int xo = 0; xo < 4; xo++){
            int xl = xo*4 + xi;
            int xg = q*16 + xl;
            float m1a = 0.f, m1b = 0.f, m2a = 0.f, m2b = 0.f;
            #pragma unroll 8
            for (int dd = 0; dd < 64; dd += 2){
                float v0 = sS[xl*64 + dd], v1 = sS[xl*64 + dd+1];
                m1a = fmaf(sEA[y*65 + dd],   v0, m1a);
                m1b = fmaf(sEA[y*65 + dd+1], v1, m1b);
                m2a = fmaf(sDV[y*65 + dd],   v0, m2a);
                m2b = fmaf(sDV[y*65 + dd+1], v1, m2b);
            }
            int o = (b*64 + xg)*64 + y;
            M1_[o] = m1a + m1b;
            M2_[o] = m2a + m2b;
        }

        if (q == 0){
            int ry = b*64 + y;
            if (xi == 0){
                float s = 0.f, s2 = 0.f;
                #pragma unroll 8
                for (int dd = 0; dd < 64; dd++){ float v = sEA[y*65+dd]; s += v; s2 = fmaf(v, v, s2); }
                SA_[ry] = s; SA2_[ry] = s2;
            } else if (xi == 1){
                const float* eprow = EP_ + base + y*64;
                float s = 0.f, s2 = 0.f;
                #pragma unroll 8
                for (int dd = 0; dd < 64; dd++){ float v = eprow[dd]; s += v; s2 = fmaf(v, v, s2); }
                SP_[ry] = s; SP2_[ry] = s2;
            } else if (xi == 2){
                float s = 0.f, s2 = 0.f;
                #pragma unroll 8
                for (int dd = 0; dd < 64; dd++){ float v = sDV[y*65+dd]; s += v; s2 = fmaf(v, v, s2); }
                SDV_[ry] = s; SDV2_[ry] = s2;
            } else {
                const float* eprow = EP_ + base + y*64;
                float sa = 0.f, sp = 0.f;
                #pragma unroll 8
                for (int dd = 0; dd < 64; dd++){
                    float dvv = sDV[y*65+dd];
                    sa = fmaf(sEA[y*65+dd], dvv, sa);
                    sp = fmaf(eprow[dd], dvv, sp);
                }
                SADV_[ry] = sa; SPDV_[ry] = sp;
            }
        }
    } else {
        float* sW   = uSm;            // 64*65
        float* sS16 = uSm + 4160;     // 16*64

        int bid = blockIdx.x - 512;
        int d = t & 63, g = t >> 6;
        int row0 = bid*16;
        int r0 = g*4;

        #pragma unroll
        for (int j = 0; j < 16; j++){
            int idx = t + j*256;
            int k = idx >> 6, col = idx & 63;
            sW[k*65 + col] = g1v[k] * W_f1[(64 + k)*64 + col];
        }
        #pragma unroll
        for (int j = 0; j < 4; j++){
            int idx = t + j*256;
            int r = idx >> 6, col = idx & 63;
            sS16[r*64 + col] = S_[(row0 + r)*64 + col];
        }
        __syncthreads();

        float x0 = 0.f, x1 = 0.f, x2 = 0.f, x3 = 0.f;
        #pragma unroll 8
        for (int k = 0; k < 64; k++){
            float w = sW[k*65 + d];
            x0 = fmaf(sS16[(r0  )*64 + k], w, x0);
            x1 = fmaf(sS16[(r0+1)*64 + k], w, x1);
            x2 = fmaf(sS16[(r0+2)*64 + k], w, x2);
            x3 = fmaf(sS16[(r0+3)*64 + k], w, x3);
        }
        SX_[(row0+r0  )*64+d] = x0;
        SX_[(row0+r0+1)*64+d] = x1;
        SX_[(row0+r0+2)*64+d] = x2;
        SX_[(row0+r0+3)*64+d] = x3;

        if (bid == 0 && g == 0){
            float sc = 0.f;
            #pragma unroll 8
            for (int k = 0; k < 64; k++) sc += sW[k*65 + d];
            SCOL_[d] = sc;
        }
    }
}

// ================= Kernel C: per-(b,4x); MUFU gelu (no LUT smem traffic) ====
#define HS 68
#define NX 4
__global__ void __launch_bounds__(256, 3)
kernelC(const float* __restrict__ W_f2, const float* __restrict__ b_f2,
        const float* __restrict__ W_f3, const float* __restrict__ b_f3,
        float* __restrict__ outV)
{
    __shared__ float4 sC4[64];
    __shared__ float sH[64*HS];
    __shared__ float sP[64][4];

    int t = threadIdx.x, d = t & 63, g = t >> 6;
    int lane = t & 31, w = t >> 5;
    int gr = lane >> 2, gc = lane & 3;
    int mt2 = w & 1;        // m-half: m-tiles {2*mt2, 2*mt2+1}
    int nq  = w >> 1;       // n-quad: cols [nq*16, nq*16+16)
    int b  = blockIdx.x >> 4;
    int x0 = (blockIdx.x & 15) * NX;
    int ryb = b*64;
    const int y0 = g*16;
    const int bbase = b*4096;

    // B fragments for 2 n-tiles (x-invariant)
    unsigned bfr[2][8][2];
    float b2v[2][2], w3v[2][2];
    #pragma unroll
    for (int nt = 0; nt < 2; nt++){
        int n = nq*16 + nt*8 + gr;
        #pragma unroll
        for (int kt = 0; kt < 8; kt++){
            bfr[nt][kt][0] = tf32_rne(W_f2[(kt*8 + gc    )*64 + n]);
            bfr[nt][kt][1] = tf32_rne(W_f2[(kt*8 + gc + 4)*64 + n]);
        }
        int c0 = nq*16 + nt*8 + 2*gc;
        b2v[nt][0] = b_f2[c0]; b2v[nt][1] = b_f2[c0+1];
        w3v[nt][0] = W_f3[c0]; w3v[nt][1] = W_f3[c0+1];
    }
    float b3  = b_f3[0];
    float scol = SCOL_[d];

    for (int xi = 0; xi < NX; xi++){
        int x  = x0 + xi;
        int bx = ryb + x;

        // ---- per-x moment scalars ----
        if (t >= 64 && t < 128){
            int y = t - 64;
            bool diag = (y == x);
            float wt   = WT_[bx*64 + y];
            float sa   = diag ? SP_  [bx] : SA_  [ryb+y];
            float sa2  = diag ? SP2_ [bx] : SA2_ [ryb+y];
            float sadv = diag ? SPDV_[bx] : SADV_[ryb+y];
            float m1   = diag ? M1P_ [bx] : M1_  [bx*64+y];
            float sdv  = SDV_ [ryb+y];
            float sdv2 = SDV2_[ryb+y];
            float m2v  = M2_  [bx*64+y];
            float sumSx = SS_[bx], sumS2x = SS2_[bx];
            float m   = (sa + sumSx + wt*sdv) * (1.0f/64.0f);
            float ex2 = (sa2 + sumS2x + wt*wt*sdv2 + 2.0f*(m1 + wt*(m2v+sadv))) * (1.0f/64.0f);
            float rstd = rsqrtf(ex2 - m*m + 1e-5f);
            sC4[y] = make_float4(rstd, rstd*wt, rstd*m, 0.f);
        }
        __syncthreads();

        // ---- phase 1: build H tile ----
        {
            float Pc  = PC_[bx*64 + d];
            float sSx = SX_[bx*64 + d];
            #pragma unroll 4
            for (int r = 0; r < 16; r++){
                int y = y0 + r;
                int idx = bbase + y*64 + d;
                const float* Aptr = (y == x) ? AP_ : AB_;
                float av = Aptr[idx];
                float dv = DB_[idx];
                float4 cc = sC4[y];
                float v = fmaf(cc.x, av + sSx, Pc);
                v = fmaf(cc.y, dv, v);
                v = fmaf(-cc.z, scol, v);
                sH[y*HS + d] = __uint_as_float(tf32_rne(gelu_as(v)));
            }
        }
        __syncthreads();

        // ---- phase 2: mma, A reused across the warp's 2 n-tiles ----
        float acc[2][2][4];
        #pragma unroll
        for (int i = 0; i < 2; i++)
            #pragma unroll
            for (int j = 0; j < 2; j++)
                acc[i][j][0] = acc[i][j][1] = acc[i][j][2] = acc[i][j][3] = 0.f;

        #pragma unroll
        for (int mi = 0; mi < 2; mi++){
            int rowb = (mt2*2 + mi)*16;
            #pragma unroll
            for (int kt = 0; kt < 8; kt++){
                int kc = kt*8 + gc;
                unsigned a0 = __float_as_uint(sH[(rowb + gr    )*HS + kc]);
                unsigned a1 = __float_as_uint(sH[(rowb + 8 + gr)*HS + kc]);
                unsigned a2 = __float_as_uint(sH[(rowb + gr    )*HS + kc + 4]);
                unsigned a3 = __float_as_uint(sH[(rowb + 8 + gr)*HS + kc + 4]);
                mma_tf32(acc[mi][0][0], acc[mi][0][1], acc[mi][0][2], acc[mi][0][3],
                         a0, a1, a2, a3, bfr[0][kt][0], bfr[0][kt][1]);
                mma_tf32(acc[mi][1][0], acc[mi][1][1], acc[mi][1][2], acc[mi][1][3],
                         a0, a1, a2, a3, bfr[1][kt][0], bfr[1][kt][1]);
            }
        }

        // ---- epilogue: b2 + gelu + w3, reduce over this warp's 16 cols ----
        #pragma unroll
        for (int mi = 0; mi < 2; mi++){
            float r0 = 0.f, r1 = 0.f;
            #pragma unroll
            for (int nt = 0; nt < 2; nt++){
                r0 = fmaf(gelu_as(acc[mi][nt][0] + b2v[nt][0]), w3v[nt][0], r0);
                r0 = fmaf(gelu_as(acc[mi][nt][1] + b2v[nt][1]), w3v[nt][1], r0);
                r1 = fmaf(gelu_as(acc[mi][nt][2] + b2v[nt][0]), w3v[nt][0], r1);
                r1 = fmaf(gelu_as(acc[mi][nt][3] + b2v[nt][1]), w3v[nt][1], r1);
            }
            r0 += __shfl_xor_sync(0xffffffffu, r0, 1);
            r0 += __shfl_xor_sync(0xffffffffu, r0, 2);
            r1 += __shfl_xor_sync(0xffffffffu, r1, 1);
            r1 += __shfl_xor_sync(0xffffffffu, r1, 2);
            if (gc == 0){
                int rowb = (mt2*2 + mi)*16;
                sP[rowb + gr][nq]     = r0;
                sP[rowb + 8 + gr][nq] = r1;
            }
        }
        __syncthreads();
        if (t < 64){
            outV[bx*64 + t] = (sP[t][0] + sP[t][1]) + (sP[t][2] + sP[t][3]) + b3;
        }
    }
}

// ================= launcher =================================================
extern "C" void kernel_launch(void* const* d_in, const int* in_sizes, int n_in,
                              void* d_out, int out_size)
{
    const float* states  = (const float*)d_in[0];
    const float* policies= (const float*)d_in[1];
    const float* actions = (const float*)d_in[2];
    const float* W_se = (const float*)d_in[3];  const float* b_se = (const float*)d_in[4];
    const float* W_k  = (const float*)d_in[5];  const float* b_k  = (const float*)d_in[6];
    const float* W_q  = (const float*)d_in[7];  const float* b_q  = (const float*)d_in[8];
    const float* W_sap= (const float*)d_in[9];  const float* b_sap= (const float*)d_in[10];
    const float* W_av = (const float*)d_in[11]; const float* b_av = (const float*)d_in[12];
    const float* g1   = (const float*)d_in[13]; const float* beta1= (const float*)d_in[14];
    const float* W_ca = (const float*)d_in[15]; const float* b_ca = (const float*)d_in[16];
    const float* g2   = (const float*)d_in[17]; const float* beta2= (const float*)d_in[18];
    const float* W_f1 = (const float*)d_in[19]; const float* b_f1 = (const float*)d_in[20];
    const float* W_f2 = (const float*)d_in[21]; const float* b_f2 = (const float*)d_in[22];
    const float* W_f3 = (const float*)d_in[23]; const float* b_f3 = (const float*)d_in[24];

    float* out  = (float*)d_out;
    float* outW = (out_size >= 2*BNN) ? (out + BNN) : nullptr;

    kernelA<<<ROWS/16, 256>>>(states, policies, actions,
                              W_se, b_se, W_k, b_k, W_q, b_q,
                              W_sap, b_sap, W_av, b_av,
                              g1, beta1, W_ca, b_ca, g2, beta2, W_f1, b_f1);
    kernelB<<<BB*2, 256>>>(outW);
    kernelB23<<<1024, 256>>>(g1, W_f1);
    kernelC<<<BB*16, 256>>>(W_f2, b_f2, W_f3, b_f3, out);
}

// round 17
// speedup vs baseline: 1.1418x; 1.1418x over previous
#include <cuda_runtime.h>
#include <math.h>

#define BB 128
#define NN 64
#define DD 64
#define ROWS (BB*NN)      // 8192 (b,n) rows
#define BNN  (BB*NN*NN)   // 524288 output rows

// ---------------- scratch (device globals: no allocations allowed) ----------
// NOTE: __align__(16) is load-bearing — several arrays are accessed via float4.
__device__ __align__(16) float K_  [ROWS*DD];
__device__ __align__(16) float Q_  [ROWS*DD];
__device__ __align__(16) float CAE_[ROWS*DD];
__device__ __align__(16) float EA_ [ROWS*DD];
__device__ __align__(16) float EP_ [ROWS*DD];
__device__ __align__(16) float AVA_[ROWS*DD];
__device__ __align__(16) float DV_ [ROWS*DD];
__device__ __align__(16) float AB_ [ROWS*DD];
__device__ __align__(16) float AP_ [ROWS*DD];
__device__ __align__(16) float DB_ [ROWS*DD];
__device__ __align__(16) float S_  [ROWS*DD];
__device__ __align__(16) float WT_ [ROWS*NN];
__device__ __align__(16) float PC_ [ROWS*DD];
__device__ __align__(16) float SX_ [ROWS*DD];
__device__ __align__(16) float SCOL_[DD];
// LN moment machinery
__device__ __align__(16) float SA_  [ROWS];
__device__ __align__(16) float SA2_ [ROWS];
__device__ __align__(16) float SP_  [ROWS];
__device__ __align__(16) float SP2_ [ROWS];
__device__ __align__(16) float SDV_ [ROWS];
__device__ __align__(16) float SDV2_[ROWS];
__device__ __align__(16) float SADV_[ROWS];
__device__ __align__(16) float SPDV_[ROWS];
__device__ __align__(16) float SS_  [ROWS];
__device__ __align__(16) float SS2_ [ROWS];
__device__ __align__(16) float M1P_ [ROWS];
__device__ __align__(16) float M1_  [ROWS*NN];
__device__ __align__(16) float M2_  [ROWS*NN];

// Precise gelu (erff) — used only to build the LUT.
__device__ __forceinline__ float gelu_exact(float x){
    return 0.5f*x*(1.0f + erff(x*0.70710678118654752f));
}

// MUFU-based gelu (A&S 7.1.26, |err|<=1.5e-7 abs) — no shared memory.
__device__ __forceinline__ float gelu_as(float x){
    float z = fabsf(x) * 0.70710678118654752f;
    float t = __fdividef(1.0f, fmaf(0.3275911f, z, 1.0f));
    float p = fmaf(t, 1.061405429f, -1.453152027f);
    p = fmaf(t, p, 1.421413741f);
    p = fmaf(t, p, -0.284496736f);
    p = fmaf(t, p, 0.254829592f);
    p = p * t;
    float e = __expf(-z*z);
    float erfz = fmaf(-p, e, 1.0f);
    float cdf  = fmaf(copysignf(erfz, x), 0.5f, 0.5f);
    return x * cdf;
}

// 768-segment piecewise-linear gelu LUT over [-6,6].
#define LUTN 768
__device__ __forceinline__ void build_gelu_lut(float2* lut, int t, int nthreads){
    for (int i = t; i < LUTN; i += nthreads){
        float x0 = (i - 384) * 0.015625f;
        float x1 = x0 + 0.015625f;
        float y0 = gelu_exact(x0);
        float y1 = gelu_exact(x1);
        float k = y1 - y0;
        lut[i] = make_float2(k, fmaf(-(float)i, k, y0));
    }
}
__device__ __forceinline__ float gelu_lut(float x, const float2* lut){
    float u = fmaf(x, 64.0f, 384.0f);
    int i = (int)u;
    i = max(0, min(i, LUTN - 1));
    float2 e = lut[i];
    return fmaf(u, e.x, e.y);
}

__device__ __forceinline__ unsigned tf32_rne(float x){
    unsigned u;
    asm("cvt.rna.tf32.f32 %0, %1;" : "=r"(u) : "f"(x));
    return u;
}

__device__ __forceinline__ void mma_tf32(float& c0, float& c1, float& c2, float& c3,
                                         unsigned a0, unsigned a1, unsigned a2, unsigned a3,
                                         unsigned b0, unsigned b1){
    asm volatile("mma.sync.aligned.m16n8k8.row.col.f32.tf32.tf32.f32 "
                 "{%0,%1,%2,%3}, {%4,%5,%6,%7}, {%8,%9}, {%0,%1,%2,%3};"
                 : "+f"(c0), "+f"(c1), "+f"(c2), "+f"(c3)
                 : "r"(a0), "r"(a1), "r"(a2), "r"(a3), "r"(b0), "r"(b1));
}

// ================= Kernel A: per-(b,n) fused encoder =========================
__global__ void __launch_bounds__(256)
kernelA(const float* __restrict__ states, const float* __restrict__ policies,
        const float* __restrict__ actions,
        const float* __restrict__ W_se, const float* __restrict__ b_se,
        const float* __restrict__ W_k,  const float* __restrict__ b_k,
        const float* __restrict__ W_q,  const float* __restrict__ b_q,
        const float* __restrict__ W_sap,const float* __restrict__ b_sap,
        const float* __restrict__ W_av, const float* __restrict__ b_av,
        const float* __restrict__ g1v,  const float* __restrict__ beta1,
        const float* __restrict__ W_ca, const float* __restrict__ b_ca,
        const float* __restrict__ g2,   const float* __restrict__ beta2,
        const float* __restrict__ W_f1, const float* __restrict__ b_f1)
{
    __shared__ float st[16][128];
    __shared__ float ac[16][32], po[16][32];
    __shared__ float sse[16][64], sea[16][64], sep[16][64], sdv[16][64];
    __shared__ float scae[16][64];
    __shared__ float sg1[64], sb1[64];
    __shared__ float red[16][2];
    __shared__ float2 sLut[LUTN];

    int t = threadIdx.x, d = t & 63, g = t >> 6;
    int lane = t & 31, wig = (t >> 5) & 1;
    int row0 = blockIdx.x*16;
    int r0 = g*4;

    build_gelu_lut(sLut, t, 256);
    #pragma unroll
    for (int j = 0; j < 8; j++){
        int idx = t + j*256;
        st[idx >> 7][idx & 127] = states[row0*128 + idx];
    }
    #pragma unroll
    for (int j = 0; j < 2; j++){
        int idx = t + j*256;
        ac[idx >> 5][idx & 31] = actions[row0*32 + idx];
        po[idx >> 5][idx & 31] = policies[row0*32 + idx];
    }
    if (t < 64) sg1[t] = g1v[t];
    else if (t < 128) sb1[t-64] = beta1[t-64];
    __syncthreads();

    float a0 = b_se[d], a1 = a0, a2 = a0, a3 = a0;
    #pragma unroll 8
    for (int k = 0; k < 128; k++){
        float w = W_se[k*64 + d];
        a0 = fmaf(st[r0  ][k], w, a0);
        a1 = fmaf(st[r0+1][k], w, a1);
        a2 = fmaf(st[r0+2][k], w, a2);
        a3 = fmaf(st[r0+3][k], w, a3);
    }
    float se0 = gelu_lut(a0, sLut), se1 = gelu_lut(a1, sLut);
    float se2 = gelu_lut(a2, sLut), se3 = gelu_lut(a3, sLut);
    sse[r0][d] = se0; sse[r0+1][d] = se1; sse[r0+2][d] = se2; sse[r0+3][d] = se3;
    __syncthreads();

    float k0 = b_k[d], k1 = k0, k2 = k0, k3 = k0;
    float q0 = b_q[d], q1 = q0, q2 = q0, q3 = q0;
    #pragma unroll 8
    for (int k = 0; k < 64; k++){
        float wk = W_k[k*64 + d];
        float wq = W_q[k*64 + d];
        float s0 = sse[r0][k], s1 = sse[r0+1][k], s2 = sse[r0+2][k], s3 = sse[r0+3][k];
        k0 = fmaf(s0, wk, k0); k1 = fmaf(s1, wk, k1); k2 = fmaf(s2, wk, k2); k3 = fmaf(s3, wk, k3);
        q0 = fmaf(s0, wq, q0); q1 = fmaf(s1, wq, q1); q2 = fmaf(s2, wq, q2); q3 = fmaf(s3, wq, q3);
    }
    K_[(row0+r0  )*64 + d] = gelu_lut(k0, sLut);
    K_[(row0+r0+1)*64 + d] = gelu_lut(k1, sLut);
    K_[(row0+r0+2)*64 + d] = gelu_lut(k2, sLut);
    K_[(row0+r0+3)*64 + d] = gelu_lut(k3, sLut);
    Q_[(row0+r0  )*64 + d] = gelu_lut(q0, sLut);
    Q_[(row0+r0+1)*64 + d] = gelu_lut(q1, sLut);
    Q_[(row0+r0+2)*64 + d] = gelu_lut(q2, sLut);
    Q_[(row0+r0+3)*64 + d] = gelu_lut(q3, sLut);

    float c0 = b_ca[d], c1 = c0, c2 = c0, c3 = c0;
    #pragma unroll 8
    for (int k = 0; k < 128; k++){
        float w = W_ca[k*64 + d];
        c0 = fmaf(st[r0  ][k], w, c0);
        c1 = fmaf(st[r0+1][k], w, c1);
        c2 = fmaf(st[r0+2][k], w, c2);
        c3 = fmaf(st[r0+3][k], w, c3);
    }
    float v0 = gelu_lut(c0, sLut) + se0, v1 = gelu_lut(c1, sLut) + se1;
    float v2 = gelu_lut(c2, sLut) + se2, v3 = gelu_lut(c3, sLut) + se3;
    {
        float s0 = v0, s1 = v1, s2 = v2, s3 = v3;
        #pragma unroll
        for (int o = 16; o > 0; o >>= 1){
            s0 += __shfl_xor_sync(0xffffffffu, s0, o);
            s1 += __shfl_xor_sync(0xffffffffu, s1, o);
            s2 += __shfl_xor_sync(0xffffffffu, s2, o);
            s3 += __shfl_xor_sync(0xffffffffu, s3, o);
        }
        if (lane == 0){ red[r0][wig]=s0; red[r0+1][wig]=s1; red[r0+2][wig]=s2; red[r0+3][wig]=s3; }
    }
    __syncthreads();
    float m0 = (red[r0][0]+red[r0][1])*(1.0f/64.0f);
    float m1v= (red[r0+1][0]+red[r0+1][1])*(1.0f/64.0f);
    float m2v= (red[r0+2][0]+red[r0+2][1])*(1.0f/64.0f);
    float m3v= (red[r0+3][0]+red[r0+3][1])*(1.0f/64.0f);
    __syncthreads();
    float e0 = v0-m0, e1 = v1-m1v, e2 = v2-m2v, e3 = v3-m3v;
    {
        float s0=e0*e0, s1=e1*e1, s2=e2*e2, s3=e3*e3;
        #pragma unroll
        for (int o = 16; o > 0; o >>= 1){
            s0 += __shfl_xor_sync(0xffffffffu, s0, o);
            s1 += __shfl_xor_sync(0xffffffffu, s1, o);
            s2 += __shfl_xor_sync(0xffffffffu, s2, o);
            s3 += __shfl_xor_sync(0xffffffffu, s3, o);
        }
        if (lane == 0){ red[r0][wig]=s0; red[r0+1][wig]=s1; red[r0+2][wig]=s2; red[r0+3][wig]=s3; }
    }
    __syncthreads();
    {
        float gd = g2[d], bd = beta2[d];
        float var0 = (red[r0][0]+red[r0][1])*(1.0f/64.0f);
        float var1 = (red[r0+1][0]+red[r0+1][1])*(1.0f/64.0f);
        float var2 = (red[r0+2][0]+red[r0+2][1])*(1.0f/64.0f);
        float var3 = (red[r0+3][0]+red[r0+3][1])*(1.0f/64.0f);
        float ca0 = e0*rsqrtf(var0+1e-5f)*gd + bd;
        float ca1 = e1*rsqrtf(var1+1e-5f)*gd + bd;
        float ca2 = e2*rsqrtf(var2+1e-5f)*gd + bd;
        float ca3 = e3*rsqrtf(var3+1e-5f)*gd + bd;
        CAE_[(row0+r0  )*64+d] = ca0;  scae[r0  ][d] = ca0;
        CAE_[(row0+r0+1)*64+d] = ca1;  scae[r0+1][d] = ca1;
        CAE_[(row0+r0+2)*64+d] = ca2;  scae[r0+2][d] = ca2;
        CAE_[(row0+r0+3)*64+d] = ca3;  scae[r0+3][d] = ca3;
    }
    __syncthreads();

    float b0 = b_sap[d], b1 = b0, b2 = b0, b3 = b0;
    #pragma unroll 8
    for (int k = 0; k < 128; k++){
        float w = W_sap[k*64 + d];
        b0 = fmaf(st[r0  ][k], w, b0);
        b1 = fmaf(st[r0+1][k], w, b1);
        b2 = fmaf(st[r0+2][k], w, b2);
        b3 = fmaf(st[r0+3][k], w, b3);
    }
    float aA0=b0,aA1=b1,aA2=b2,aA3=b3, aP0=b0,aP1=b1,aP2=b2,aP3=b3;
    #pragma unroll 8
    for (int k = 0; k < 32; k++){
        float w = W_sap[(128 + k)*64 + d];
        aA0 = fmaf(ac[r0  ][k], w, aA0); aP0 = fmaf(po[r0  ][k], w, aP0);
        aA1 = fmaf(ac[r0+1][k], w, aA1); aP1 = fmaf(po[r0+1][k], w, aP1);
        aA2 = fmaf(ac[r0+2][k], w, aA2); aP2 = fmaf(po[r0+2][k], w, aP2);
        aA3 = fmaf(ac[r0+3][k], w, aA3); aP3 = fmaf(po[r0+3][k], w, aP3);
    }
    float ea0=gelu_lut(aA0,sLut), ea1=gelu_lut(aA1,sLut), ea2=gelu_lut(aA2,sLut), ea3=gelu_lut(aA3,sLut);
    float ep0=gelu_lut(aP0,sLut), ep1=gelu_lut(aP1,sLut), ep2=gelu_lut(aP2,sLut), ep3=gelu_lut(aP3,sLut);
    sea[r0][d]=ea0; sea[r0+1][d]=ea1; sea[r0+2][d]=ea2; sea[r0+3][d]=ea3;
    sep[r0][d]=ep0; sep[r0+1][d]=ep1; sep[r0+2][d]=ep2; sep[r0+3][d]=ep3;
    EA_[(row0+r0  )*64+d]=ea0; EA_[(row0+r0+1)*64+d]=ea1; EA_[(row0+r0+2)*64+d]=ea2; EA_[(row0+r0+3)*64+d]=ea3;
    EP_[(row0+r0  )*64+d]=ep0; EP_[(row0+r0+1)*64+d]=ep1; EP_[(row0+r0+2)*64+d]=ep2; EP_[(row0+r0+3)*64+d]=ep3;
    __syncthreads();

    float vA0=b_av[d],vA1=vA0,vA2=vA0,vA3=vA0, vP0=vA0,vP1=vA0,vP2=vA0,vP3=vA0;
    #pragma unroll 8
    for (int k = 0; k < 64; k++){
        float w = W_av[k*64 + d];
        vA0 = fmaf(sea[r0  ][k], w, vA0); vP0 = fmaf(sep[r0  ][k], w, vP0);
        vA1 = fmaf(sea[r0+1][k], w, vA1); vP1 = fmaf(sep[r0+1][k], w, vP1);
        vA2 = fmaf(sea[r0+2][k], w, vA2); vP2 = fmaf(sep[r0+2][k], w, vP2);
        vA3 = fmaf(sea[r0+3][k], w, vA3); vP3 = fmaf(sep[r0+3][k], w, vP3);
    }
    float av0=gelu_lut(vA0,sLut), av1=gelu_lut(vA1,sLut), av2=gelu_lut(vA2,sLut), av3=gelu_lut(vA3,sLut);
    float dv0=gelu_lut(vP0,sLut)-av0, dv1=gelu_lut(vP1,sLut)-av1;
    float dv2=gelu_lut(vP2,sLut)-av2, dv3=gelu_lut(vP3,sLut)-av3;
    AVA_[(row0+r0  )*64+d]=av0; AVA_[(row0+r0+1)*64+d]=av1; AVA_[(row0+r0+2)*64+d]=av2; AVA_[(row0+r0+3)*64+d]=av3;
    DV_ [(row0+r0  )*64+d]=dv0; DV_ [(row0+r0+1)*64+d]=dv1; DV_ [(row0+r0+2)*64+d]=dv2; DV_ [(row0+r0+3)*64+d]=dv3;
    sdv[r0][d]=dv0; sdv[r0+1][d]=dv1; sdv[r0+2][d]=dv2; sdv[r0+3][d]=dv3;
    __syncthreads();

    float fa0=0,fa1=0,fa2=0,fa3=0, fp0=0,fp1=0,fp2=0,fp3=0, fd0=0,fd1=0,fd2=0,fd3=0;
    #pragma unroll 8
    for (int k = 0; k < 64; k++){
        float wb = W_f1[(64 + k)*64 + d] * sg1[k];
        fa0 = fmaf(sea[r0  ][k], wb, fa0); fp0 = fmaf(sep[r0  ][k], wb, fp0); fd0 = fmaf(sdv[r0  ][k], wb, fd0);
        fa1 = fmaf(sea[r0+1][k], wb, fa1); fp1 = fmaf(sep[r0+1][k], wb, fp1); fd1 = fmaf(sdv[r0+1][k], wb, fd1);
        fa2 = fmaf(sea[r0+2][k], wb, fa2); fp2 = fmaf(sep[r0+2][k], wb, fp2); fd2 = fmaf(sdv[r0+2][k], wb, fd2);
        fa3 = fmaf(sea[r0+3][k], wb, fa3); fp3 = fmaf(sep[r0+3][k], wb, fp3); fd3 = fmaf(sdv[r0+3][k], wb, fd3);
    }
    AB_[(row0+r0  )*64+d]=fa0; AB_[(row0+r0+1)*64+d]=fa1; AB_[(row0+r0+2)*64+d]=fa2; AB_[(row0+r0+3)*64+d]=fa3;
    AP_[(row0+r0  )*64+d]=fp0; AP_[(row0+r0+1)*64+d]=fp1; AP_[(row0+r0+2)*64+d]=fp2; AP_[(row0+r0+3)*64+d]=fp3;
    DB_[(row0+r0  )*64+d]=fd0; DB_[(row0+r0+1)*64+d]=fd1; DB_[(row0+r0+2)*64+d]=fd2; DB_[(row0+r0+3)*64+d]=fd3;

    float pc0 = b_f1[d], pc1 = pc0, pc2 = pc0, pc3 = pc0, pcc = 0.f;
    #pragma unroll 8
    for (int k = 0; k < 64; k++){
        float wt = W_f1[k*64 + d];
        float wb = W_f1[(64 + k)*64 + d];
        pcc = fmaf(sb1[k], wb, pcc);
        pc0 = fmaf(scae[r0  ][k], wt, pc0);
        pc1 = fmaf(scae[r0+1][k], wt, pc1);
        pc2 = fmaf(scae[r0+2][k], wt, pc2);
        pc3 = fmaf(scae[r0+3][k], wt, pc3);
    }
    PC_[(row0+r0  )*64+d] = pc0 + pcc;
    PC_[(row0+r0+1)*64+d] = pc1 + pcc;
    PC_[(row0+r0+2)*64+d] = pc2 + pcc;
    PC_[(row0+r0+3)*64+d] = pc3 + pcc;
}

// ================= Kernel B: per-b softmax + S + per-x stats ================
__global__ void __launch_bounds__(256)
kernelB(float* __restrict__ outW)
{
    __shared__ float sK[64*65];
    __shared__ float sA[64*65];
    __shared__ float sq[4][64];
    __shared__ float sw[4][64];
    __shared__ float red[4][2];
    __shared__ float red3[4][2][3];

    int t = threadIdx.x, d = t & 63, g = t >> 6;
    int lane = t & 31, wig = (t >> 5) & 1;
    int b = blockIdx.x >> 1, half = blockIdx.x & 1;
    const int base = b*NN*DD;

    for (int jj = 0; jj < 16; jj++){
        int j = jj*4 + g;
        sK[j*65 + d] = K_  [base + j*64 + d];
        sA[j*65 + d] = AVA_[base + j*64 + d];
    }
    __syncthreads();

    for (int xi = 0; xi < 8; xi++){
        int x = half*32 + xi*4 + g;
        int rowx = b*64 + x;
        sq[g][d] = Q_[rowx*64 + d];
        __syncthreads();

        float s0 = 0.f, s1 = 0.f;
        #pragma unroll 8
        for (int k = 0; k < 64; k += 2){
            s0 = fmaf(sq[g][k],   sK[d*65 + k],   s0);
            s1 = fmaf(sq[g][k+1], sK[d*65 + k+1], s1);
        }
        float s = (s0 + s1) * 0.125f;

        float mx = s;
        #pragma unroll
        for (int o = 16; o > 0; o >>= 1) mx = fmaxf(mx, __shfl_xor_sync(0xffffffffu, mx, o));
        if (lane == 0) red[g][wig] = mx;
        __syncthreads();
        mx = fmaxf(red[g][0], red[g][1]);
        float e  = expf(s - mx);
        float ss = e;
        #pragma unroll
        for (int o = 16; o > 0; o >>= 1) ss += __shfl_xor_sync(0xffffffffu, ss, o);
        __syncthreads();
        if (lane == 0) red[g][wig] = ss;
        __syncthreads();
        float w = e / (red[g][0] + red[g][1]);

        sw[g][d] = w;
        WT_[rowx*64 + d] = w;
        if (outW) outW[rowx*64 + d] = w;
        __syncthreads();

        float S0 = 0.f, S1 = 0.f;
        #pragma unroll 8
        for (int i = 0; i < 64; i += 2){
            S0 = fmaf(sw[g][i],   sA[(i  )*65 + d], S0);
            S1 = fmaf(sw[g][i+1], sA[(i+1)*65 + d], S1);
        }
        float Sd = S0 + S1;
        S_[rowx*64 + d] = Sd;

        float ep = EP_[rowx*64 + d];
        float t1 = Sd, t2 = Sd*Sd, t3 = ep*Sd;
        #pragma unroll
        for (int o = 16; o > 0; o >>= 1){
            t1 += __shfl_xor_sync(0xffffffffu, t1, o);
            t2 += __shfl_xor_sync(0xffffffffu, t2, o);
            t3 += __shfl_xor_sync(0xffffffffu, t3, o);
        }
        if (lane == 0){ red3[g][wig][0]=t1; red3[g][wig][1]=t2; red3[g][wig][2]=t3; }
        __syncthreads();
        if (d == 0){
            SS_ [rowx] = red3[g][0][0] + red3[g][1][0];
            SS2_[rowx] = red3[g][0][1] + red3[g][1][1];
            M1P_[rowx] = red3[g][0][2] + red3[g][1][2];
        }
        __syncthreads();
    }
}

// ================= Kernel B23: fused B2 (cross-dots/moments) + B3 (SX) ======
__global__ void __launch_bounds__(256)
kernelB23(const float* __restrict__ g1v, const float* __restrict__ W_f1)
{
    __shared__ __align__(16) float uSm[9344];   // 37376 bytes

    int t = threadIdx.x;

    if (blockIdx.x < 512){
        float* sEA = uSm;             // 64*65
        float* sDV = uSm + 4160;      // 64*65
        float* sS  = uSm + 8320;      // 16*64

        int xi = t >> 6, y = t & 63;
        int b = blockIdx.x >> 2, q = blockIdx.x & 3;
        const int base = b*4096;

        for (int jj = 0; jj < 16; jj++){
            int j = jj*4 + xi;
            sEA[j*65 + y] = EA_[base + j*64 + y];
            sDV[j*65 + y] = DV_[base + j*64 + y];
        }
        for (int s4 = 0; s4 < 4; s4++){
            int xl = s4*4 + xi;
            sS[xl*64 + y] = S_[(b*64 + q*16 + xl)*64 + y];
        }
        __syncthreads();

        #pragma unroll
        for (int xo = 0; xo < 4; xo++){
            int xl = xo*4 + xi;
            int xg = q*16 + xl;
            float m1a = 0.f, m1b = 0.f, m2a = 0.f, m2b = 0.f;
            #pragma unroll 8
            for (int dd = 0; dd < 64; dd += 2){
                float v0 = sS[xl*64 + dd], v1 = sS[xl*64 + dd+1];
                m1a = fmaf(sEA[y*65 + dd],   v0, m1a);
                m1b = fmaf(sEA[y*65 + dd+1], v1, m1b);
                m2a = fmaf(sDV[y*65 + dd],   v0, m2a);
                m2b = fmaf(sDV[y*65 + dd+1], v1, m2b);
            }
            int o = (b*64 + xg)*64 + y;
            M1_[o] = m1a + m1b;
            M2_[o] = m2a + m2b;
        }

        if (q == 0){
            int ry = b*64 + y;
            if (xi == 0){
                float s = 0.f, s2 = 0.f;
                #pragma unroll 8
                for (int dd = 0; dd < 64; dd++){ float v = sEA[y*65+dd]; s += v; s2 = fmaf(v, v, s2); }
                SA_[ry] = s; SA2_[ry] = s2;
            } else if (xi == 1){
                const float* eprow = EP_ + base + y*64;
                float s = 0.f, s2 = 0.f;
                #pragma unroll 8
                for (int dd = 0; dd < 64; dd++){ float v = eprow[dd]; s += v; s2 = fmaf(v, v, s2); }
                SP_[ry] = s; SP2_[ry] = s2;
            } else if (xi == 2){
                float s = 0.f, s2 = 0.f;
                #pragma unroll 8
                for (int dd = 0; dd < 64; dd++){ float v = sDV[y*65+dd]; s += v; s2 = fmaf(v, v, s2); }
                SDV_[ry] = s; SDV2_[ry] = s2;
            } else {
                const float* eprow = EP_ + base + y*64;
                float sa = 0.f, sp = 0.f;
                #pragma unroll 8
                for (int dd = 0; dd < 64; dd++){
                    float dvv = sDV[y*65+dd];
                    sa = fmaf(sEA[y*65+dd], dvv, sa);
                    sp = fmaf(eprow[dd], dvv, sp);
                }
                SADV_[ry] = sa; SPDV_[ry] = sp;
            }
        }
    } else {
        float* sW   = uSm;            // 64*65
        float* sS16 = uSm + 4160;     // 16*64

        int bid = blockIdx.x - 512;
        int d = t & 63, g = t >> 6;
        int row0 = bid*16;
        int r0 = g*4;

        #pragma unroll
        for (int j = 0; j < 16; j++){
            int idx = t + j*256;
            int k = idx >> 6, col = idx & 63;
            sW[k*65 + col] = g1v[k] * W_f1[(64 + k)*64 + col];
        }
        #pragma unroll
        for (int j = 0; j < 4; j++){
            int idx = t + j*256;
            int r = idx >> 6, col = idx & 63;
            sS16[r*64 + col] = S_[(row0 + r)*64 + col];
        }
        __syncthreads();

        float x0 = 0.f, x1 = 0.f, x2 = 0.f, x3 = 0.f;
        #pragma unroll 8
        for (int k = 0; k < 64; k++){
            float w = sW[k*65 + d];
            x0 = fmaf(sS16[(r0  )*64 + k], w, x0);
            x1 = fmaf(sS16[(r0+1)*64 + k], w, x1);
            x2 = fmaf(sS16[(r0+2)*64 + k], w, x2);
            x3 = fmaf(sS16[(r0+3)*64 + k], w, x3);
        }
        SX_[(row0+r0  )*64+d] = x0;
        SX_[(row0+r0+1)*64+d] = x1;
        SX_[(row0+r0+2)*64+d] = x2;
        SX_[(row0+r0+3)*64+d] = x3;

        if (bid == 0 && g == 0){
            float sc = 0.f;
            #pragma unroll 8
            for (int k = 0; k < 64; k++) sc += sW[k*65 + d];
            SCOL_[d] = sc;
        }
    }
}

// ================= Kernel C: hybrid gelu (LUT phase-1, MUFU epilogue), =====
// float4 phase-1, warp=(m-half,n-quad) MMA tiling.
#define HS 68
#define NX 4
__global__ void __launch_bounds__(256, 3)
kernelC(const float* __restrict__ W_f2, const float* __restrict__ b_f2,
        const float* __restrict__ W_f3, const float* __restrict__ b_f3,
        float* __restrict__ outV)
{
    __shared__ float4 sC4[64];
    __shared__ __align__(16) float sH[64*HS];
    __shared__ float sP[64][4];
    __shared__ float2 sLut[LUTN];

    int t = threadIdx.x, g = t >> 6;
    int lane = t & 31, w = t >> 5;
    int gr = lane >> 2, gc = lane & 3;
    int mt2 = w & 1;        // m-half
    int nq  = w >> 1;       // n-quad
    int b  = blockIdx.x >> 4;
    int x0 = (blockIdx.x & 15) * NX;
    int ryb = b*64;
    const int bbase = b*4096;

    // phase-1 mapping: 4 rows x 4 consecutive d per thread
    int dg = (t & 15) * 4;  // d-group base
    int yb = t >> 4;        // base row; rows yb + 16*j

    build_gelu_lut(sLut, t, 256);

    // B fragments for 2 n-tiles (x-invariant)
    unsigned bfr[2][8][2];
    float b2v[2][2], w3v[2][2];
    #pragma unroll
    for (int nt = 0; nt < 2; nt++){
        int n = nq*16 + nt*8 + gr;
        #pragma unroll
        for (int kt = 0; kt < 8; kt++){
            bfr[nt][kt][0] = tf32_rne(W_f2[(kt*8 + gc    )*64 + n]);
            bfr[nt][kt][1] = tf32_rne(W_f2[(kt*8 + gc + 4)*64 + n]);
        }
        int c0 = nq*16 + nt*8 + 2*gc;
        b2v[nt][0] = b_f2[c0]; b2v[nt][1] = b_f2[c0+1];
        w3v[nt][0] = W_f3[c0]; w3v[nt][1] = W_f3[c0+1];
    }
    float b3  = b_f3[0];
    float4 scol4 = *(const float4*)&SCOL_[dg];

    for (int xi = 0; xi < NX; xi++){
        int x  = x0 + xi;
        int bx = ryb + x;

        // ---- per-x moment scalars ----
        if (t >= 64 && t < 128){
            int y = t - 64;
            bool diag = (y == x);
            float wt   = WT_[bx*64 + y];
            float sa   = diag ? SP_  [bx] : SA_  [ryb+y];
            float sa2  = diag ? SP2_ [bx] : SA2_ [ryb+y];
            float sadv = diag ? SPDV_[bx] : SADV_[ryb+y];
            float m1   = diag ? M1P_ [bx] : M1_  [bx*64+y];
            float sdv  = SDV_ [ryb+y];
            float sdv2 = SDV2_[ryb+y];
            float m2v  = M2_  [bx*64+y];
            float sumSx = SS_[bx], sumS2x = SS2_[bx];
            float m   = (sa + sumSx + wt*sdv) * (1.0f/64.0f);
            float ex2 = (sa2 + sumS2x + wt*wt*sdv2 + 2.0f*(m1 + wt*(m2v+sadv))) * (1.0f/64.0f);
            float rstd = rsqrtf(ex2 - m*m + 1e-5f);
            sC4[y] = make_float4(rstd, rstd*wt, rstd*m, 0.f);
        }
        __syncthreads();

        // ---- phase 1: build H tile (float4, LUT gelu) ----
        {
            float4 Pc4 = *(const float4*)&PC_[bx*64 + dg];
            float4 SX4 = *(const float4*)&SX_[bx*64 + dg];
            #pragma unroll
            for (int j = 0; j < 4; j++){
                int y = yb + 16*j;
                const float* Aptr = (y == x) ? AP_ : AB_;
                float4 a4 = *(const float4*)&Aptr[bbase + y*64 + dg];
                float4 d4 = *(const float4*)&DB_ [bbase + y*64 + dg];
                float4 cc = sC4[y];
                float v0 = fmaf(cc.x, a4.x + SX4.x, Pc4.x); v0 = fmaf(cc.y, d4.x, v0); v0 = fmaf(-cc.z, scol4.x, v0);
                float v1 = fmaf(cc.x, a4.y + SX4.y, Pc4.y); v1 = fmaf(cc.y, d4.y, v1); v1 = fmaf(-cc.z, scol4.y, v1);
                float v2 = fmaf(cc.x, a4.z + SX4.z, Pc4.z); v2 = fmaf(cc.y, d4.z, v2); v2 = fmaf(-cc.z, scol4.z, v2);
                float v3 = fmaf(cc.x, a4.w + SX4.w, Pc4.w); v3 = fmaf(cc.y, d4.w, v3); v3 = fmaf(-cc.z, scol4.w, v3);
                float4 h4;
                h4.x = __uint_as_float(tf32_rne(gelu_lut(v0, sLut)));
                h4.y = __uint_as_float(tf32_rne(gelu_lut(v1, sLut)));
                h4.z = __uint_as_float(tf32_rne(gelu_lut(v2, sLut)));
                h4.w = __uint_as_float(tf32_rne(gelu_lut(v3, sLut)));
                *(float4*)&sH[y*HS + dg] = h4;
            }
        }
        __syncthreads();

        // ---- phase 2: mma, A reused across the warp's 2 n-tiles ----
        float acc[2][2][4];
        #pragma unroll
        for (int i = 0; i < 2; i++)
            #pragma unroll
            for (int j = 0; j < 2; j++)
                acc[i][j][0] = acc[i][j][1] = acc[i][j][2] = acc[i][j][3] = 0.f;

        #pragma unroll
        for (int mi = 0; mi < 2; mi++){
            int rowb = (mt2*2 + mi)*16;
            #pragma unroll
            for (int kt = 0; kt < 8; kt++){
                int kc = kt*8 + gc;
                unsigned a0 = __float_as_uint(sH[(rowb + gr    )*HS + kc]);
                unsigned a1 = __float_as_uint(sH[(rowb + 8 + gr)*HS + kc]);
                unsigned a2 = __float_as_uint(sH[(rowb + gr    )*HS + kc + 4]);
                unsigned a3 = __float_as_uint(sH[(rowb + 8 + gr)*HS + kc + 4]);
                mma_tf32(acc[mi][0][0], acc[mi][0][1], acc[mi][0][2], acc[mi][0][3],
                         a0, a1, a2, a3, bfr[0][kt][0], bfr[0][kt][1]);
                mma_tf32(acc[mi][1][0], acc[mi][1][1], acc[mi][1][2], acc[mi][1][3],
                         a0, a1, a2, a3, bfr[1][kt][0], bfr[1][kt][1]);
            }
        }

        // ---- epilogue: b2 + MUFU gelu + w3, reduce over warp's 16 cols ----
        #pragma unroll
        for (int mi = 0; mi < 2; mi++){
            float r0 = 0.f, r1 = 0.f;
            #pragma unroll
            for (int nt = 0; nt < 2; nt++){
                r0 = fmaf(gelu_as(acc[mi][nt][0] + b2v[nt][0]), w3v[nt][0], r0);
                r0 = fmaf(gelu_as(acc[mi][nt][1] + b2v[nt][1]), w3v[nt][1], r0);
                r1 = fmaf(gelu_as(acc[mi][nt][2] + b2v[nt][0]), w3v[nt][0], r1);
                r1 = fmaf(gelu_as(acc[mi][nt][3] + b2v[nt][1]), w3v[nt][1], r1);
            }
            r0 += __shfl_xor_sync(0xffffffffu, r0, 1);
            r0 += __shfl_xor_sync(0xffffffffu, r0, 2);
            r1 += __shfl_xor_sync(0xffffffffu, r1, 1);
            r1 += __shfl_xor_sync(0xffffffffu, r1, 2);
            if (gc == 0){
                int rowb = (mt2*2 + mi)*16;
                sP[rowb + gr][nq]     = r0;
                sP[rowb + 8 + gr][nq] = r1;
            }
        }
        __syncthreads();
        if (t < 64){
            outV[bx*64 + t] = (sP[t][0] + sP[t][1]) + (sP[t][2] + sP[t][3]) + b3;
        }
    }
}

// ================= launcher =================================================
extern "C" void kernel_launch(void* const* d_in, const int* in_sizes, int n_in,
                              void* d_out, int out_size)
{
    const float* states  = (const float*)d_in[0];
    const float* policies= (const float*)d_in[1];
    const float* actions = (const float*)d_in[2];
    const float* W_se = (const float*)d_in[3];  const float* b_se = (const float*)d_in[4];
    const float* W_k  = (const float*)d_in[5];  const float* b_k  = (const float*)d_in[6];
    const float* W_q  = (const float*)d_in[7];  const float* b_q  = (const float*)d_in[8];
    const float* W_sap= (const float*)d_in[9];  const float* b_sap= (const float*)d_in[10];
    const float* W_av = (const float*)d_in[11]; const float* b_av = (const float*)d_in[12];
    const float* g1   = (const float*)d_in[13]; const float* beta1= (const float*)d_in[14];
    const float* W_ca = (const float*)d_in[15]; const float* b_ca = (const float*)d_in[16];
    const float* g2   = (const float*)d_in[17]; const float* beta2= (const float*)d_in[18];
    const float* W_f1 = (const float*)d_in[19]; const float* b_f1 = (const float*)d_in[20];
    const float* W_f2 = (const float*)d_in[21]; const float* b_f2 = (const float*)d_in[22];
    const float* W_f3 = (const float*)d_in[23]; const float* b_f3 = (const float*)d_in[24];

    float* out  = (float*)d_out;
    float* outW = (out_size >= 2*BNN) ? (out + BNN) : nullptr;

    kernelA<<<ROWS/16, 256>>>(states, policies, actions,
                              W_se, b_se, W_k, b_k, W_q, b_q,
                              W_sap, b_sap, W_av, b_av,
                              g1, beta1, W_ca, b_ca, g2, beta2, W_f1, b_f1);
    kernelB<<<BB*2, 256>>>(outW);
    kernelB23<<<1024, 256>>>(g1, W_f1);
    kernelC<<<BB*16, 256>>>(W_f2, b_f2, W_f3, b_f3, out);
}